// round 1
// baseline (speedup 1.0000x reference)
#include <cuda_runtime.h>
#include <cuda_bf16.h>

#define SZ     64
#define HW     4096
#define BB     16
#define STEPS  409   // int(0.1 * 64 * 64)

// ---------------- global scratch (no allocations allowed) ----------------
__device__ unsigned short d_sel_log[BB * STEPS];        // selected cell per (batch, step)
__device__ unsigned char  d_updcnt[BB * STEPS];         // #parent updates per (batch, step)
__device__ unsigned short d_updcell[BB * STEPS * 8];    // updated cells per (batch, step)
__device__ unsigned int   d_mask[STEPS];                // per-step solved bitmask across batches
__device__ volatile unsigned int d_prog[BB];            // per-batch completed-step counter
__device__ int            d_goal[BB];                   // goal flat index per batch

// f = 0.5*g + 0.5*h  (muls by 0.5 are exact);  key = exp(-f * 0.125)
__device__ __forceinline__ float keyval(float g, float h) {
    float f = __fadd_rn(__fmul_rn(0.5f, g), __fmul_rn(0.5f, h));
    return expf(__fmul_rn(-f, 0.125f));
}

// ---------------- kernel 0: zero the cross-batch coordination state -------
__global__ void init_kernel() {
    int t = threadIdx.x;
    for (int s = t; s < STEPS; s += blockDim.x) d_mask[s] = 0u;
    if (t < BB) d_prog[t] = 0u;
}

// ---------------- kernel 1: per-batch A* simulation (one CTA per batch) ---
__global__ void __launch_bounds__(512, 1)
astar_kernel(const float* __restrict__ cost,
             const float* __restrict__ start,
             const float* __restrict__ goalm,
             const float* __restrict__ obst) {
    extern __shared__ unsigned char smraw[];
    float*         s_key   = (float*)smraw;            // 4096 f32: exp(-f/8)*sm
    float*         s_g     = s_key + HW;               // 4096 f32
    float*         s_h     = s_g + HW;                 // 4096 f32: heuristic + cost
    unsigned char* s_state = (unsigned char*)(s_h + HW); // bit0 open, bit1 closed, bit2 free
    float*         s_pv    = (float*)(s_state + HW);   // 16 warp partial values
    int*           s_pi    = (int*)(s_pv + 16);        // 16 warp partial indices
    int*           s_misc  = (int*)(s_pi + 16);        // [0]=goal idx, [1]=break flag

    const int b    = blockIdx.x;
    const int tid  = threadIdx.x;
    const int lane = tid & 31;
    const int warp = tid >> 5;

    const float* cb = cost  + b * HW;
    const float* sb = start + b * HW;
    const float* gb = goalm + b * HW;
    const float* ob = obst  + b * HW;

    if (tid == 0) s_misc[1] = 0;
    // goal index (one-hot -> unique)
    for (int c = tid; c < HW; c += 512)
        if (gb[c] > 0.5f) s_misc[0] = c;
    __syncthreads();
    const int goalIdx = s_misc[0];
    if (tid == 0) d_goal[b] = goalIdx;
    const int grow = goalIdx >> 6, gcol = goalIdx & 63;

    // per-cell init
    for (int c = tid; c < HW; c += 512) {
        int r = c >> 6, col = c & 63;
        int di = abs(r - grow), dj = abs(col - gcol);
        int cheb = (di > dj) ? di : dj;                       // sum - min = max
        float euc = sqrtf((float)(di * di + dj * dj));
        float h = __fadd_rn((float)cheb, __fmul_rn(0.001f, euc));
        h = __fadd_rn(h, cb[c]);                              // h = heuristic + cost
        s_h[c] = h;
        s_g[c] = 0.0f;
        unsigned char st = 0;
        if (ob[c] > 0.5f) st |= 4;
        bool open = (sb[c] > 0.5f);
        if (open) st |= 1;
        s_state[c] = st;
        s_key[c] = open ? keyval(0.0f, h) : 0.0f;
    }

    // neighbor offsets (3x3 minus center)
    const int dri[8] = {-1,-1,-1, 0, 0, 1, 1, 1};
    const int drj[8] = {-1, 0, 1,-1, 1,-1, 0, 1};

    // early-exit bookkeeping (lives in tid 511's registers)
    int scanpos = 0, tfound = -1;

    for (int step = 0; step < STEPS; ++step) {
        __syncthreads();                  // previous updates visible; break flag uniform
        if (s_misc[1]) break;

        // ---- block argmax over s_key (value desc, index asc) ----
        const float4* kp = (const float4*)s_key;
        float4 a0 = kp[tid * 2], a1 = kp[tid * 2 + 1];
        int   base = tid * 8;
        float bv = -1.0f; int bi = 0;
        if (a0.x > bv) { bv = a0.x; bi = base + 0; }
        if (a0.y > bv) { bv = a0.y; bi = base + 1; }
        if (a0.z > bv) { bv = a0.z; bi = base + 2; }
        if (a0.w > bv) { bv = a0.w; bi = base + 3; }
        if (a1.x > bv) { bv = a1.x; bi = base + 4; }
        if (a1.y > bv) { bv = a1.y; bi = base + 5; }
        if (a1.z > bv) { bv = a1.z; bi = base + 6; }
        if (a1.w > bv) { bv = a1.w; bi = base + 7; }
        #pragma unroll
        for (int off = 16; off; off >>= 1) {
            float ov = __shfl_down_sync(0xffffffffu, bv, off);
            int   oi = __shfl_down_sync(0xffffffffu, bi, off);
            if (ov > bv || (ov == bv && oi < bi)) { bv = ov; bi = oi; }
        }
        if (lane == 0) { s_pv[warp] = bv; s_pi[warp] = bi; }
        __syncthreads();

        if (warp == 0) {
            float v = (lane < 16) ? s_pv[lane] : -2.0f;
            int   i2 = (lane < 16) ? s_pi[lane] : 0;
            #pragma unroll
            for (int off = 8; off; off >>= 1) {
                float ov = __shfl_down_sync(0xffffffffu, v, off);
                int   oi = __shfl_down_sync(0xffffffffu, i2, off);
                if (ov > v || (ov == v && oi < i2)) { v = ov; i2 = oi; }
            }
            const int sel = __shfl_sync(0xffffffffu, i2, 0);
            const bool solved = (sel == goalIdx);
            const float g2 = __fadd_rn(s_g[sel], cb[sel]);   // g[sel] + cost[sel]

            bool upd = false; int nb = 0;
            if (lane < 8) {
                int ni = (sel >> 6) + dri[lane];
                int nj = (sel & 63) + drj[lane];
                if ((unsigned)ni < 64u && (unsigned)nj < 64u) {
                    nb = (ni << 6) | nj;
                    unsigned char st = s_state[nb];
                    if (st & 4) {                             // free cell
                        bool open   = st & 1;
                        bool closed = st & 2;
                        if ((!open && !closed) || (open && (s_g[nb] > g2)))
                            upd = true;
                    }
                }
            }
            unsigned m = __ballot_sync(0xffffffffu, upd);
            if (upd) {
                s_g[nb]  = g2;
                s_state[nb] |= 1;                             // add to open
                s_key[nb] = keyval(g2, s_h[nb]);
                int pos = __popc(m & ((1u << lane) - 1));
                d_updcell[(b * STEPS + step) * 8 + pos] = (unsigned short)nb;
            }
            if (lane == 0) {
                d_updcnt[b * STEPS + step]  = (unsigned char)__popc(m);
                d_sel_log[b * STEPS + step] = (unsigned short)sel;
                unsigned char st = s_state[sel] | 2;          // close sel
                if (!solved) { st &= 0xFE; s_key[sel] = 0.0f; } // remove from open if unsolved
                s_state[sel] = st;
                if (solved) atomicOr(&d_mask[step], 1u << b);
                __threadfence();
                d_prog[b] = (unsigned)(step + 1);
            }
        } else if (tid == 511) {
            // opportunistic early exit: never waits, only breaks when t_stop is proven passed
            if ((step & 7) == 7) {
                if (tfound < 0) {
                    unsigned mn = 0xffffffffu;
                    #pragma unroll
                    for (int q = 0; q < BB; q++) {
                        unsigned p = d_prog[q];
                        if (p < mn) mn = p;
                    }
                    while (scanpos < (int)mn) {
                        unsigned mv = *(volatile unsigned*)&d_mask[scanpos];
                        if (mv == 0xFFFFu) { tfound = scanpos; break; }
                        scanpos++;
                    }
                }
                if (tfound >= 0 && step >= tfound) s_misc[1] = 1;
            }
        }
    }
}

// ---------------- kernel 2: reconstruct hist/parents/path, write output ---
__global__ void __launch_bounds__(512, 1)
finalize_kernel(float* __restrict__ out) {
    __shared__ unsigned int  s_pm[HW];     // packed (step+1)<<12 | parent
    __shared__ unsigned char s_hist[HW];
    __shared__ unsigned char s_path[HW];
    __shared__ int s_ts;

    const int b = blockIdx.x, tid = threadIdx.x;

    if (tid == 0) s_ts = STEPS;
    for (int c = tid; c < HW; c += 512) { s_pm[c] = 0u; s_hist[c] = 0; s_path[c] = 0; }
    __syncthreads();

    int lm = STEPS;
    for (int s = tid; s < STEPS; s += 512)
        if (d_mask[s] == 0xFFFFu && s < lm) lm = s;
    atomicMin(&s_ts, lm);
    __syncthreads();
    int ts = s_ts;
    if (ts == STEPS) ts = STEPS - 1;       // never all-solved -> t_stop = steps-1

    // replay logs up to t_stop (last writer wins via atomicMax on packed step)
    for (int s = tid; s <= ts; s += 512) {
        int sel = d_sel_log[b * STEPS + s];
        s_hist[sel] = 1;
        int cnt = d_updcnt[b * STEPS + s];
        unsigned packed = ((unsigned)(s + 1) << 12) | (unsigned)sel;
        for (int k = 0; k < cnt; k++)
            atomicMax(&s_pm[d_updcell[(b * STEPS + s) * 8 + k]], packed);
    }
    __syncthreads();

    const int goal = d_goal[b];
    if (tid == 0) {
        s_path[goal] = 1;                                  // path init = goal one-hot
        unsigned pv = s_pm[goal];
        int loc = pv ? (int)(pv & 4095u) : goal;           // parents default to goal idx
        for (int i = 0; i < ts; i++) {                     // fori(0,steps) with i<t_stop guard
            s_path[loc] = 1;
            unsigned q = s_pm[loc];
            loc = q ? (int)(q & 4095u) : goal;
        }
    }
    __syncthreads();

    for (int c = tid; c < HW; c += 512) {
        out[b * HW + c]            = s_hist[c] ? 1.0f : 0.0f;   // hist (B,1,64,64)
        out[BB * HW + b * HW + c]  = s_path[c] ? 1.0f : 0.0f;   // path_maps (B,1,64,64)
    }
}

// ---------------- launch -------------------------------------------------
extern "C" void kernel_launch(void* const* d_in, const int* in_sizes, int n_in,
                              void* d_out, int out_size) {
    const float* cost  = (const float*)d_in[0];
    const float* start = (const float*)d_in[1];
    const float* goal  = (const float*)d_in[2];
    const float* obst  = (const float*)d_in[3];
    float* out = (float*)d_out;

    const size_t smem = 3 * HW * sizeof(float) + HW      // key,g,h + state
                      + 16 * sizeof(float) + 16 * sizeof(int) + 2 * sizeof(int);
    cudaFuncSetAttribute(astar_kernel, cudaFuncAttributeMaxDynamicSharedMemorySize, (int)smem);

    init_kernel<<<1, 512>>>();
    astar_kernel<<<BB, 512, smem>>>(cost, start, goal, obst);
    finalize_kernel<<<BB, 512>>>(out);
}

// round 2
// speedup vs baseline: 1.5612x; 1.5612x over previous
#include <cuda_runtime.h>

#define HW    4096
#define BB    16
#define STEPS 409   // int(0.1 * 64 * 64)

typedef unsigned long long ull;
typedef unsigned int uint;

// cross-CTA coordination (zeroed in-kernel via generation handshake)
__device__ uint d_mask[STEPS];   // per-step solved bitmask across batches
__device__ uint d_prog[BB];      // per-batch completed-step counter
__device__ uint d_ready;         // monotone generation counter across launches

__device__ __forceinline__ uint rmax(uint v){uint d;asm("redux.sync.max.u32 %0, %1, 0xffffffff;":"=r"(d):"r"(v));return d;}
__device__ __forceinline__ uint rmin(uint v){uint d;asm("redux.sync.min.u32 %0, %1, 0xffffffff;":"=r"(d):"r"(v));return d;}

// f = 0.5*g + 0.5*h ; key = exp(-f * 0.125)
__device__ __forceinline__ float keyval(float g, float h){
    float f = __fadd_rn(__fmul_rn(0.5f, g), __fmul_rn(0.5f, h));
    return expf(__fmul_rn(-0.125f, f));
}

// ---- dynamic SMEM layout (bytes) ----
#define OFF_KEY    0        // float[4096]
#define OFF_GPAIR  16384    // float2[4096] {g, cost}; overlaid by pm/hist/path in finalize
#define OFF_HC     49152    // float[4096] heuristic+cost
#define OFF_STATE  65536    // uchar[4096] bit0 open, bit1 closed, bit2 free
#define OFF_ROWP   69632    // ull[64] per-row packed max (keybits<<32 | 0xFFFF-idx)
#define OFF_SELLOG 70144    // u16[512]
#define OFF_UPDCNT 71168    // u8[512]
#define OFF_UPDCEL 71680    // u16[512*8]
#define OFF_MISC   79872    // int[0]=goal, int[1]=t_stop
#define SMEM_TOTAL 79936

__global__ void __launch_bounds__(512, 1)
astar_fused(const float* __restrict__ cost, const float* __restrict__ start,
            const float* __restrict__ goalm, const float* __restrict__ obst,
            float* __restrict__ out)
{
    extern __shared__ char smraw[];
    float*          s_key    = (float*)(smraw + OFF_KEY);
    float2*         s_gp     = (float2*)(smraw + OFF_GPAIR);
    float*          s_hc     = (float*)(smraw + OFF_HC);
    unsigned char*  s_state  = (unsigned char*)(smraw + OFF_STATE);
    ull*            s_rowp   = (ull*)(smraw + OFF_ROWP);
    unsigned short* s_sellog = (unsigned short*)(smraw + OFF_SELLOG);
    unsigned char*  s_updcnt = (unsigned char*)(smraw + OFF_UPDCNT);
    unsigned short* s_updcel = (unsigned short*)(smraw + OFF_UPDCEL);
    int*            s_misc   = (int*)(smraw + OFF_MISC);

    const int b    = blockIdx.x;
    const int tid  = threadIdx.x;
    const int lane = tid & 31;
    const int warp = tid >> 5;

    const float* cb = cost  + b * HW;
    const float* sb = start + b * HW;
    const float* gb = goalm + b * HW;
    const float* ob = obst  + b * HW;

    // ---- zero this CTA's slice of coordination state + find goal ----
    {
        int s = b + tid * BB;
        if (s < STEPS) d_mask[s] = 0u;
        if (tid == 0) d_prog[b] = 0u;
    }
    for (int c = tid; c < HW; c += 512)
        if (gb[c] > 0.5f) s_misc[0] = c;
    __threadfence();            // make zeroing visible before handshake
    __syncthreads();
    if (tid == 0) {
        uint old = atomicAdd(&d_ready, 1u);
        uint target = ((old >> 4) + 1u) << 4;   // 16 CTAs per run-generation
        while (*((volatile uint*)&d_ready) < target) {}
        __threadfence();
    }
    __syncthreads();

    const int goalIdx = s_misc[0];
    const int grow = goalIdx >> 6, gcol = goalIdx & 63;

    // ---- per-cell init ----
    for (int c = tid; c < HW; c += 512) {
        int r = c >> 6, col = c & 63;
        int di = abs(r - grow), dj = abs(col - gcol);
        int cheb = (di > dj) ? di : dj;                 // sum - min = max
        float euc = sqrtf((float)(di * di + dj * dj));
        float h = __fadd_rn((float)cheb, __fmul_rn(0.001f, euc));
        float cc = cb[c];
        h = __fadd_rn(h, cc);
        s_hc[c] = h;
        s_gp[c] = make_float2(0.0f, cc);
        unsigned char st = 0;
        if (ob[c] > 0.5f) st |= 4;
        bool open = (sb[c] > 0.5f);
        if (open) st |= 1;
        s_state[c] = st;
        s_key[c] = open ? keyval(0.0f, h) : 0.0f;
    }
    __syncthreads();

    // ---- build per-row packed maxima (16 warps x 4 rows) ----
    for (int k = 0; k < 4; k++) {
        int r = (warp << 2) + k, base = r << 6;
        float a = s_key[base + lane], e = s_key[base + 32 + lane];
        ull q0 = ((ull)__float_as_uint(a) << 32) | (ull)(uint)(0xFFFF - (base + lane));
        ull q1 = ((ull)__float_as_uint(e) << 32) | (ull)(uint)(0xFFFF - (base + 32 + lane));
        ull q = q0 > q1 ? q0 : q1;
        uint hi = (uint)(q >> 32);
        uint mq = rmax(hi);
        uint lo = (hi == mq) ? (uint)q : 0u;
        uint lq = rmax(lo);
        if (lane == 0) s_rowp[r] = ((ull)mq << 32) | lq;
    }
    __syncthreads();

    // ================= single-warp driver loop =================
    if (warp == 0) {
        const uint FULL = (1u << BB) - 1u;
        int tfound = -1, scanpos = 0, step;
        for (step = 0; step < STEPS; ++step) {
            // ---- global argmax from 64 row maxima (exact tie: smallest idx) ----
            ull rp0 = s_rowp[lane], rp1 = s_rowp[lane + 32];
            ull p = rp0 > rp1 ? rp0 : rp1;
            uint hi = (uint)(p >> 32);
            uint m = rmax(hi);
            uint lo = (hi == m) ? (uint)p : 0u;
            uint lm = rmax(lo);
            int sel  = 0xFFFF - (int)lm;
            int srow = sel >> 6, scol = sel & 63;
            bool solved = (sel == goalIdx);
            float2 gp = s_gp[sel];
            float g2 = __fadd_rn(gp.x, gp.y);           // g[sel] + cost[sel]
            int rb = srow << 6;
            float k0 = s_key[rb + lane];                // pre-update row snapshot
            float k1 = s_key[rb + 32 + lane];

            // ---- neighbor evaluation (lanes 0-7) ----
            bool upd = false; int nb = 0; float nk = 0.0f; ull npack = 0;
            if (lane < 8) {
                int nidx = lane + (lane >= 4 ? 1 : 0);  // skip center
                int ni = srow + nidx / 3 - 1;
                int nj = scol + nidx % 3 - 1;
                if ((uint)ni < 64u && (uint)nj < 64u) {
                    nb = (ni << 6) | nj;
                    unsigned char st = s_state[nb];
                    if (st & 4u) {
                        bool open = st & 1u, closed = st & 2u;
                        float gn = s_gp[nb].x;
                        if ((!open && !closed) || (open && gn > g2)) upd = true;
                    }
                }
            }
            if (upd) {
                nk = keyval(g2, s_hc[nb]);
                npack = ((ull)__float_as_uint(nk) << 32) | (ull)(uint)(0xFFFF - nb);
            }
            uint m8 = __ballot_sync(0xffffffffu, upd);
            // horizontal (same-row) neighbor packs, for in-register rescan merge
            ull pL = __shfl_sync(0xffffffffu, npack, 3);
            ull pR = __shfl_sync(0xffffffffu, npack, 4);
            bool uL = (m8 >> 3) & 1u, uR = (m8 >> 4) & 1u;

            if (!solved) {
                // remove sel from open: rescan its row on the pre-update snapshot,
                // substituting the (only possible) same-row key increases in registers
                ull p0 = ((ull)__float_as_uint(k0) << 32) | (ull)(uint)(0xFFFF - (rb + lane));
                ull p1 = ((ull)__float_as_uint(k1) << 32) | (ull)(uint)(0xFFFF - (rb + 32 + lane));
                if (scol < 32) { if (lane == scol) p0 = 0; }
                else           { if (lane == scol - 32) p1 = 0; }
                if (uL) { int c = scol - 1; if (c < 32) { if (lane == c && pL > p0) p0 = pL; }
                          else { if (lane == c - 32 && pL > p1) p1 = pL; } }
                if (uR) { int c = scol + 1; if (c < 32) { if (lane == c && pR > p0) p0 = pR; }
                          else { if (lane == c - 32 && pR > p1) p1 = pR; } }
                ull pp = p0 > p1 ? p0 : p1;
                uint h2 = (uint)(pp >> 32);
                uint mm = rmax(h2);
                uint l2 = (h2 == mm) ? (uint)pp : 0u;
                uint lm2 = rmax(l2);
                if (lane == 0) {
                    s_rowp[srow] = ((ull)mm << 32) | lm2;
                    s_key[sel] = 0.0f;
                    s_state[sel] = (unsigned char)((s_state[sel] & ~1u) | 2u);
                }
            } else if (lane == 0) {
                s_state[sel] |= 2u;
                atomicOr(&d_mask[step], 1u << b);
            }

            // ---- apply neighbor updates (monotone key increases) ----
            if (upd) {
                s_key[nb] = nk;
                s_gp[nb].x = g2;
                s_state[nb] |= 1u;
                atomicMax(&s_rowp[nb >> 6], npack);    // safe vs rescan STS (<= final)
                int pos = __popc(m8 & ((1u << lane) - 1u));
                s_updcel[step * 8 + pos] = (unsigned short)nb;
            }
            if (lane == 0) {
                s_sellog[step] = (unsigned short)sel;
                s_updcnt[step] = (unsigned char)__popc(m8);
            }

            // ---- periodic progress publish + opportunistic t_stop detection ----
            if (((step & 7) == 7) && lane == 0) {
                __threadfence();
                *((volatile uint*)&d_prog[b]) = (uint)(step + 1);
            }
            if (((step & 15) == 15) && tfound < 0) {
                uint pv = (lane < BB) ? ((volatile uint*)d_prog)[lane] : 0xffffffffu;
                uint mn = rmin(pv);
                while (scanpos < (int)mn) {
                    int idx = scanpos + lane;
                    uint mv = (idx < (int)mn) ? ((volatile uint*)d_mask)[idx] : 0u;
                    uint bal = __ballot_sync(0xffffffffu, mv == FULL);
                    if (bal) { tfound = scanpos + __ffs(bal) - 1; break; }
                    scanpos += 32; if (scanpos > (int)mn) scanpos = (int)mn;
                }
            }
            __syncwarp();                               // cross-lane SMEM visibility
            if (tfound >= 0 && step >= tfound) { step++; break; }
        }

        // final progress publish (guarantees other CTAs' t_stop spin terminates)
        if (lane == 0) {
            __threadfence();
            *((volatile uint*)&d_prog[b]) = (uint)step;
        }

        // ---- resolve global t_stop ----
        int ts = tfound;
        if (ts < 0) {
            while (true) {
                uint pv = (lane < BB) ? ((volatile uint*)d_prog)[lane] : 0xffffffffu;
                uint mn = rmin(pv);
                bool fnd = false;
                while (scanpos < (int)mn) {
                    int idx = scanpos + lane;
                    uint mv = (idx < (int)mn) ? ((volatile uint*)d_mask)[idx] : 0u;
                    uint bal = __ballot_sync(0xffffffffu, mv == FULL);
                    if (bal) { ts = scanpos + __ffs(bal) - 1; fnd = true; break; }
                    scanpos += 32; if (scanpos > (int)mn) scanpos = (int)mn;
                }
                if (fnd) break;
                if (mn >= (uint)STEPS) { ts = STEPS - 1; break; }
            }
        }
        if (lane == 0) s_misc[1] = ts;
    }
    __syncthreads();   // idle warps sleep here during the loop

    // ================= finalize (all 512 threads, SMEM logs) =================
    uint*          pm   = (uint*)(smraw + OFF_GPAIR);            // overlay, 16KB
    unsigned char* hist = (unsigned char*)(smraw + OFF_GPAIR + 16384);
    unsigned char* path = (unsigned char*)(smraw + OFF_GPAIR + 20480);

    for (int c = tid; c < HW; c += 512) { pm[c] = 0u; hist[c] = 0; path[c] = 0; }
    __syncthreads();

    const int ts = s_misc[1];
    for (int s = tid; s <= ts; s += 512) {
        int sl = s_sellog[s];
        hist[sl] = 1;
        int cnt = s_updcnt[s];
        uint packed = ((uint)(s + 1) << 12) | (uint)sl;          // last-writer wins
        for (int k = 0; k < cnt; k++)
            atomicMax(&pm[s_updcel[s * 8 + k]], packed);
    }
    __syncthreads();

    if (tid == 0) {
        path[goalIdx] = 1;
        uint pv = pm[goalIdx];
        int loc = pv ? (int)(pv & 4095u) : goalIdx;
        for (int i = 0; i < ts; i++) {
            if (path[loc]) break;    // deterministic chase: revisit => all future marks redundant
            path[loc] = 1;
            uint q = pm[loc];
            loc = q ? (int)(q & 4095u) : goalIdx;
        }
    }
    __syncthreads();

    for (int c = tid; c < HW; c += 512) {
        out[b * HW + c]           = hist[c] ? 1.0f : 0.0f;   // hist (B,1,64,64)
        out[BB * HW + b * HW + c] = path[c] ? 1.0f : 0.0f;   // path_maps (B,1,64,64)
    }
}

// ---------------- launch -------------------------------------------------
extern "C" void kernel_launch(void* const* d_in, const int* in_sizes, int n_in,
                              void* d_out, int out_size) {
    const float* cost  = (const float*)d_in[0];
    const float* start = (const float*)d_in[1];
    const float* goal  = (const float*)d_in[2];
    const float* obst  = (const float*)d_in[3];
    float* out = (float*)d_out;

    cudaFuncSetAttribute(astar_fused, cudaFuncAttributeMaxDynamicSharedMemorySize, SMEM_TOTAL);
    astar_fused<<<BB, 512, SMEM_TOTAL>>>(cost, start, goal, obst, out);
}